// round 13
// baseline (speedup 1.0000x reference)
#include <cuda_runtime.h>
#include <cuda_bf16.h>
#include <cstdint>

#define BB 16
#define HH 180
#define WW 240
#define NC (BB*HH*WW)      /* 691200 full-res cells            */
#define HV (HH/2)          /* 90                               */
#define WV (WW/2)          /* 120                              */
#define VPB (HV*WV)        /* 10800 voxels per batch           */
#define NV (BB*VPB)        /* 172800 half-res voxels           */

#define TILE_EV    1024
#define TILE_BYTES (TILE_EV * 20)   /* 20480 B per tile */

// Scratch (__device__ globals — no allocations allowed).
// INVARIANT: g_ct is all-zero at kernel_launch entry (BSS zero-init on load;
// finalize_kernel re-zeroes every cell it reads, and its reads partition g_ct).
__device__ float2   g_ct[NC];      // per full-res cell: (count, tsum_raw)
__device__ unsigned g_tmax[BB];    // per-batch max(t) as uint bits (t >= 0)

// ---------------------------------------------------------------------------
__device__ __forceinline__ uint32_t smem_u32(const void* p) {
    uint32_t a;
    asm("{ .reg .u64 t; cvta.to.shared.u64 t, %1; cvt.u32.u64 %0, t; }"
        : "=r"(a) : "l"(p));
    return a;
}
__device__ __forceinline__ void mbar_init(uint32_t mb, unsigned cnt) {
    asm volatile("mbarrier.init.shared.b64 [%0], %1;" :: "r"(mb), "r"(cnt) : "memory");
}
__device__ __forceinline__ void mbar_expect_tx(uint32_t mb, unsigned bytes) {
    asm volatile("mbarrier.arrive.expect_tx.shared.b64 _, [%0], %1;"
                 :: "r"(mb), "r"(bytes) : "memory");
}
__device__ __forceinline__ void bulk_g2s(uint32_t dst, const void* src,
                                         unsigned bytes, uint32_t mb) {
    asm volatile("cp.async.bulk.shared::cluster.global.mbarrier::complete_tx::bytes "
                 "[%0], [%1], %2, [%3];"
                 :: "r"(dst), "l"(src), "r"(bytes), "r"(mb) : "memory");
}
__device__ __forceinline__ void mbar_wait(uint32_t mb, unsigned phase) {
    asm volatile(
        "{\n\t"
        ".reg .pred P1;\n\t"
        "WAIT_%=:\n\t"
        "mbarrier.try_wait.parity.acquire.cta.shared::cta.b64 P1, [%0], %1, 0x989680;\n\t"
        "@P1 bra DONE_%=;\n\t"
        "bra WAIT_%=;\n\t"
        "DONE_%=:\n\t"
        "}"
        :: "r"(mb), "r"(phase) : "memory");
}

// ---------------------------------------------------------------------------
// Scatter with TMA-staged (cp.async.bulk) double-buffered event tiles (R11).
__global__ void __launch_bounds__(256) scatter_kernel(
    const float* __restrict__ ev, int n, int nTiles)
{
    __shared__ __align__(128) float sbuf[2][TILE_EV * 5];   // 2 x 20 KB
    __shared__ __align__(8) unsigned long long mbar[2];
    __shared__ unsigned smax[BB];

    const unsigned FULL = 0xffffffffu;
    const int NB = gridDim.x;
    int lane = threadIdx.x & 31;
    unsigned loc = 0;  // lane l (<16) carries running max-bits for batch l

    long long totBytes = (long long)n * 20;
    const char* evb = reinterpret_cast<const char*>(ev);

    int myTiles = (blockIdx.x < nTiles) ? (nTiles - blockIdx.x + NB - 1) / NB : 0;

    uint32_t mb[2]  = { smem_u32(&mbar[0]), smem_u32(&mbar[1]) };
    uint32_t sba[2] = { smem_u32(&sbuf[0][0]), smem_u32(&sbuf[1][0]) };

    if (threadIdx.x == 0) {
        mbar_init(mb[0], 1);
        mbar_init(mb[1], 1);
    }
    if (threadIdx.x < BB) smax[threadIdx.x] = 0u;
    __syncthreads();

    if (threadIdx.x == 0) {
        #pragma unroll
        for (int j = 0; j < 2; ++j) {
            if (j < myTiles) {
                long long base = ((long long)blockIdx.x + (long long)j * NB) * TILE_BYTES;
                unsigned sz  = (unsigned)min((long long)TILE_BYTES, totBytes - base);
                unsigned m16 = sz & ~15u;
                mbar_expect_tx(mb[j], m16);
                bulk_g2s(sba[j], evb + base, m16, mb[j]);
            }
        }
    }

    for (int j = 0; j < myTiles; ++j) {
        int s = j & 1;
        mbar_wait(mb[s], (unsigned)((j >> 1) & 1));

        int tile = blockIdx.x + j * NB;
        long long baseEv = (long long)tile * TILE_EV;
        long long base   = baseEv * 20;
        unsigned  sz     = (unsigned)min((long long)TILE_BYTES, totBytes - base);
        int evFull = (int)((sz & ~15u) / 20);
        const float* sf = sbuf[s];

        #pragma unroll
        for (int q = 0; q < 4; ++q) {
            int le = threadIdx.x + q * 256;
            long long e = baseEv + le;
            bool valid = (e < (long long)n);
            float x = 0.f, y = 0.f, t = 0.f, b = 0.f;
            if (valid) {
                if (le < evFull) {                  // staged path (smem)
                    int sidx = 5 * le;
                    x = sf[sidx + 0];
                    y = sf[sidx + 1];
                    t = sf[sidx + 2];
                    b = sf[sidx + 4];
                } else {                            // rare 16B-alignment tail
                    const float* p = ev + e * 5;
                    x = __ldg(p + 0); y = __ldg(p + 1);
                    t = __ldg(p + 2); b = __ldg(p + 4);
                }
            }
            int bi = (int)b, xi = (int)x, yi = (int)y;

            if (valid) {
                // single fused atomic per event: (count, raw t) into full-res cell
                int idx_c = xi + WW * yi + (WW * HH) * bi;
                if ((unsigned)idx_c < (unsigned)NC)
                    asm volatile("red.global.add.v2.f32 [%0], {%1, %2};"
                                 :: "l"(&g_ct[idx_c]), "f"(1.0f), "f"(t) : "memory");
            }

            // per-batch time max: b sorted -> warps almost always batch-uniform
            unsigned tb = __float_as_uint(t);
            int b0 = __shfl_sync(FULL, bi, 0);
            if (__all_sync(FULL, bi == b0)) {
                unsigned wm = __reduce_max_sync(FULL, tb);
                if (lane == b0) loc = max(loc, wm);
            } else {
                for (int l = 0; l < 32; ++l) {
                    int      bl = __shfl_sync(FULL, bi, l);
                    unsigned tl = __shfl_sync(FULL, tb, l);
                    if (lane == bl) loc = max(loc, tl);
                }
            }
        }
        __syncthreads();

        int nj = j + 2;
        if (nj < myTiles && threadIdx.x == 0) {
            long long nbase = ((long long)blockIdx.x + (long long)nj * NB) * TILE_BYTES;
            unsigned nsz  = (unsigned)min((long long)TILE_BYTES, totBytes - nbase);
            unsigned m16  = nsz & ~15u;
            mbar_expect_tx(mb[s], m16);
            bulk_g2s(sba[s], evb + nbase, m16, mb[s]);
        }
    }

    if (lane < BB && loc) atomicMax(&smax[lane], loc);
    __syncthreads();
    if (threadIdx.x < BB && smax[threadIdx.x])
        atomicMax(&g_tmax[threadIdx.x], smax[threadIdx.x]);
}

// ---------------------------------------------------------------------------
// Self-cleaning finalize. Thread v=(k,ii,jj) owns exactly the cells it
// aggregates (a perfect partition of g_ct):
//   even pair: row 2ii, cols 2jj..2jj+1                       (always)
//   odd  pair: re+120 if jj>=60 (row 2ii+1, cols 2jj-120..)   — same batch
//              re-120 if jj<60  (row 2ii-1 cols 120+2jj; for ii==0 this is
//              batch k-1 row 179 — spill-in; absent when k==0)
//   orphan: k==15,ii==0,jj<60 additionally owns batch-15 row 179 col 120+2jj
// For each owned pair it: writes container, pushes its diff_x/diff_y
// contribution (target voxel is uniformly v for the even pair, v-60 for the
// odd pair, v+10740 for the orphan), accumulates counter/timer, then ZEROES
// the cells — restoring the g_ct==0 invariant with no init kernel.
__global__ void finalize_kernel(float* __restrict__ out) {
    int v = blockIdx.x * blockDim.x + threadIdx.x;
    if (v >= NV) return;

    float* cont    = out;
    float* counter = out + NC;
    float* timer   = out + NC + NV;
    float* dxo     = out + NC + 2 * NV;
    float* dyo     = out + NC + 3 * NV;
    float4* Cq = reinterpret_cast<float4*>(g_ct);   // 2 cells per float4
    const float4 Z4 = make_float4(0.f, 0.f, 0.f, 0.f);

    int k  = v / VPB;
    int rr = v - k * VPB;
    int ii = rr / WV;
    int jj = rr - ii * WV;
    int re = k * (HH * WW) + (2 * ii) * WW + 2 * jj;   // even-row pair base (even)

    // ---- even pair (own tile, row 2ii) ----
    float4 e4 = Cq[re >> 1];
    Cq[re >> 1] = Z4;
    reinterpret_cast<float2*>(cont + re)[0] = make_float2(e4.x, e4.z);
    atomicAdd(&dxo[v], e4.x - e4.z);
    atomicAdd(&dyo[v], e4.x + e4.z);

    float Tk = __uint_as_float(g_tmax[k]);
    if (Tk == 0.0f) Tk = 1.0f;

    float cnt = e4.x + e4.z;
    float tn  = (e4.y + e4.w) / Tk;

    // ---- odd pair (owned; target voxel is always v-60) ----
    bool lowj  = (jj < WV / 2);
    bool spill = lowj && (ii == 0);              // comes from batch k-1
    if (!(spill && k == 0)) {
        int oidx = re + (lowj ? -120 : 120);
        float4 o4 = Cq[oidx >> 1];
        Cq[oidx >> 1] = Z4;
        reinterpret_cast<float2*>(cont + oidx)[0] = make_float2(o4.x, o4.z);
        atomicAdd(&dxo[v - 60],  o4.x - o4.z);
        atomicAdd(&dyo[v - 60], -(o4.x + o4.z));
        float To = Tk;
        if (spill) {
            To = __uint_as_float(g_tmax[k - 1]);
            if (To == 0.0f) To = 1.0f;
        }
        cnt += o4.x + o4.z;
        tn  += (o4.y + o4.w) / To;
    }

    // ---- orphan pair: batch-15 row 179 cols 120+2jj (dropped from counter) ----
    if (spill && k == BB - 1) {
        int orph = (BB - 1) * (HH * WW) + (HH - 1) * WW + 120 + 2 * jj;
        float4 q4 = Cq[orph >> 1];
        Cq[orph >> 1] = Z4;
        reinterpret_cast<float2*>(cont + orph)[0] = make_float2(q4.x, q4.z);
        atomicAdd(&dxo[v + 10740],  q4.x - q4.z);
        atomicAdd(&dyo[v + 10740], -(q4.x + q4.z));
    }

    counter[v] = cnt;
    timer[v]   = tn / (cnt == 0.0f ? 1.0f : cnt);
}

// ---------------------------------------------------------------------------
extern "C" void kernel_launch(void* const* d_in, const int* in_sizes, int n_in,
                              void* d_out, int out_size)
{
    const float* ev = (const float*)d_in[0];
    int n = in_sizes[0] / 5;
    float* out = (float*)d_out;

    // g_ct needs NO init (self-cleaning finalize). Zero tmax + diff outputs.
    void* p_tm = nullptr;  cudaGetSymbolAddress(&p_tm, g_tmax);
    cudaMemsetAsync(p_tm, 0, sizeof(unsigned) * BB);
    cudaMemsetAsync(out + NC + 2 * NV, 0, sizeof(float) * 2 * NV);

    int nTiles = (n + TILE_EV - 1) / TILE_EV;
    scatter_kernel<<<760, 256>>>(ev, n, nTiles);
    finalize_kernel<<<(NV + 255) / 256, 256>>>(out);
}

// round 14
// speedup vs baseline: 1.1518x; 1.1518x over previous
#include <cuda_runtime.h>
#include <cuda_bf16.h>
#include <cstdint>

#define BB 16
#define HH 180
#define WW 240
#define NC (BB*HH*WW)      /* 691200 full-res cells            */
#define HV (HH/2)          /* 90                               */
#define WV (WW/2)          /* 120                              */
#define VPB (HV*WV)        /* 10800 voxels per batch           */
#define NV (BB*VPB)        /* 172800 half-res voxels           */

#define TILE_EV    1024
#define TILE_BYTES (TILE_EV * 20)   /* 20480 B per tile */
#define GRID_SC    760              /* 5 resident blocks/SM x 152 SMs (fits 148 too) */

// Scratch (__device__ globals — no allocations allowed)
__device__ float2   g_ct[NC];      // per full-res cell: (count, tsum_raw)
// g_small: [0]=grid-barrier counter, [2..17]=per-batch tmax bits.
// Zeroed by one 128 B memset node per replay.
__device__ unsigned g_small[32];

// ---------------------------------------------------------------------------
__device__ __forceinline__ uint32_t smem_u32(const void* p) {
    uint32_t a;
    asm("{ .reg .u64 t; cvta.to.shared.u64 t, %1; cvt.u32.u64 %0, t; }"
        : "=r"(a) : "l"(p));
    return a;
}
__device__ __forceinline__ void mbar_init(uint32_t mb, unsigned cnt) {
    asm volatile("mbarrier.init.shared.b64 [%0], %1;" :: "r"(mb), "r"(cnt) : "memory");
}
__device__ __forceinline__ void mbar_expect_tx(uint32_t mb, unsigned bytes) {
    asm volatile("mbarrier.arrive.expect_tx.shared.b64 _, [%0], %1;"
                 :: "r"(mb), "r"(bytes) : "memory");
}
__device__ __forceinline__ void bulk_g2s(uint32_t dst, const void* src,
                                         unsigned bytes, uint32_t mb) {
    asm volatile("cp.async.bulk.shared::cluster.global.mbarrier::complete_tx::bytes "
                 "[%0], [%1], %2, [%3];"
                 :: "r"(dst), "l"(src), "r"(bytes), "r"(mb) : "memory");
}
__device__ __forceinline__ void mbar_wait(uint32_t mb, unsigned phase) {
    asm volatile(
        "{\n\t"
        ".reg .pred P1;\n\t"
        "WAIT_%=:\n\t"
        "mbarrier.try_wait.parity.acquire.cta.shared::cta.b64 P1, [%0], %1, 0x989680;\n\t"
        "@P1 bra DONE_%=;\n\t"
        "bra WAIT_%=;\n\t"
        "DONE_%=:\n\t"
        "}"
        :: "r"(mb), "r"(phase) : "memory");
}
__device__ __forceinline__ void grid_barrier(unsigned* bar, unsigned nb) {
    __syncthreads();
    if (threadIdx.x == 0) {
        __threadfence();                       // release phase-0 zero stores
        unsigned arrived = atomicAdd(bar, 1) + 1;
        if (arrived < nb) {
            while (atomicAdd(bar, 0u) < nb) __nanosleep(64);
        }
        __threadfence();                       // acquire others' zero stores
    }
    __syncthreads();
}

// ---------------------------------------------------------------------------
// Scatter with (a) in-kernel zero phase hidden under the TMA prologue and
// (b) TMA-staged (cp.async.bulk) double-buffered event tiles (R11 mainloop).
__global__ void __launch_bounds__(256) scatter_kernel(
    const float* __restrict__ ev, int n, int nTiles)
{
    __shared__ __align__(128) float sbuf[2][TILE_EV * 5];   // 2 x 20 KB
    __shared__ __align__(8) unsigned long long mbar[2];
    __shared__ unsigned smax[BB];

    const unsigned FULL = 0xffffffffu;
    const int NB = gridDim.x;
    int lane = threadIdx.x & 31;
    unsigned loc = 0;  // lane l (<16) carries running max-bits for batch l

    long long totBytes = (long long)n * 20;
    const char* evb = reinterpret_cast<const char*>(ev);

    int myTiles = (blockIdx.x < nTiles) ? (nTiles - blockIdx.x + NB - 1) / NB : 0;

    uint32_t mb[2]  = { smem_u32(&mbar[0]), smem_u32(&mbar[1]) };
    uint32_t sba[2] = { smem_u32(&sbuf[0][0]), smem_u32(&sbuf[1][0]) };

    if (threadIdx.x == 0) {
        mbar_init(mb[0], 1);
        mbar_init(mb[1], 1);
    }
    if (threadIdx.x < BB) smax[threadIdx.x] = 0u;
    __syncthreads();

    // prologue copies FIRST (they don't touch g_ct) — their latency hides the
    // zero phase + grid barrier below
    if (threadIdx.x == 0) {
        #pragma unroll
        for (int j = 0; j < 2; ++j) {
            if (j < myTiles) {
                long long base = ((long long)blockIdx.x + (long long)j * NB) * TILE_BYTES;
                unsigned sz  = (unsigned)min((long long)TILE_BYTES, totBytes - base);
                unsigned m16 = sz & ~15u;
                mbar_expect_tx(mb[j], m16);
                bulk_g2s(sba[j], evb + base, m16, mb[j]);
            }
        }
    }

    // ---- phase 0: zero g_ct (grid-stride), then grid barrier ----
    {
        float4* z = reinterpret_cast<float4*>(g_ct);
        int gtid = blockIdx.x * 256 + threadIdx.x;
        int gnum = NB * 256;
        for (int j = gtid; j < NC / 2; j += gnum)
            z[j] = make_float4(0.f, 0.f, 0.f, 0.f);
    }
    grid_barrier(&g_small[0], NB);

    // ---- phase 1: red loop (R11, unchanged) ----
    for (int j = 0; j < myTiles; ++j) {
        int s = j & 1;
        mbar_wait(mb[s], (unsigned)((j >> 1) & 1));

        int tile = blockIdx.x + j * NB;
        long long baseEv = (long long)tile * TILE_EV;
        long long base   = baseEv * 20;
        unsigned  sz     = (unsigned)min((long long)TILE_BYTES, totBytes - base);
        int evFull = (int)((sz & ~15u) / 20);   // events fully covered by the copy
        const float* sf = sbuf[s];

        #pragma unroll
        for (int q = 0; q < 4; ++q) {
            int le = threadIdx.x + q * 256;
            long long e = baseEv + le;
            bool valid = (e < (long long)n);
            float x = 0.f, y = 0.f, t = 0.f, b = 0.f;
            if (valid) {
                if (le < evFull) {                  // staged path (smem)
                    int sidx = 5 * le;
                    x = sf[sidx + 0];
                    y = sf[sidx + 1];
                    t = sf[sidx + 2];
                    b = sf[sidx + 4];
                } else {                            // rare 16B-alignment tail
                    const float* p = ev + e * 5;
                    x = __ldg(p + 0); y = __ldg(p + 1);
                    t = __ldg(p + 2); b = __ldg(p + 4);
                }
            }
            int bi = (int)b, xi = (int)x, yi = (int)y;

            if (valid) {
                // single fused atomic per event: (count, raw t) into full-res cell
                int idx_c = xi + WW * yi + (WW * HH) * bi;
                if ((unsigned)idx_c < (unsigned)NC)
                    asm volatile("red.global.add.v2.f32 [%0], {%1, %2};"
                                 :: "l"(&g_ct[idx_c]), "f"(1.0f), "f"(t) : "memory");
            }

            // per-batch time max: b sorted -> warps almost always batch-uniform
            unsigned tb = __float_as_uint(t);
            int b0 = __shfl_sync(FULL, bi, 0);
            if (__all_sync(FULL, bi == b0)) {
                unsigned wm = __reduce_max_sync(FULL, tb);
                if (lane == b0) loc = max(loc, wm);
            } else {
                for (int l = 0; l < 32; ++l) {
                    int      bl = __shfl_sync(FULL, bi, l);
                    unsigned tl = __shfl_sync(FULL, tb, l);
                    if (lane == bl) loc = max(loc, tl);
                }
            }
        }
        __syncthreads();   // everyone done reading buf[s]

        int nj = j + 2;    // refill this buffer
        if (nj < myTiles && threadIdx.x == 0) {
            long long nbase = ((long long)blockIdx.x + (long long)nj * NB) * TILE_BYTES;
            unsigned nsz  = (unsigned)min((long long)TILE_BYTES, totBytes - nbase);
            unsigned m16  = nsz & ~15u;
            mbar_expect_tx(mb[s], m16);
            bulk_g2s(sba[s], evb + nbase, m16, mb[s]);
        }
    }

    // tmax epilogue
    if (lane < BB && loc) atomicMax(&smax[lane], loc);
    __syncthreads();
    if (threadIdx.x < BB && smax[threadIdx.x])
        atomicMax(&g_small[2 + threadIdx.x], smax[threadIdx.x]);
}

// ---------------------------------------------------------------------------
// Gather finalize (R11-proven shape). One thread per half-res voxel.
// Voxel (k, ii, jj) aggregates, per the reference's
// idx_k = floor(x/2) + 60*y + 10800*b quirk:
//   even row y=2ii, cols [2jj, 2jj+1]                       (always)
//   jj >= 60: odd row y=2ii+1, cols [2jj-120, 2jj-119]      (same batch)
//   jj <  60, ii >= 1: odd row y=2ii-1, cols [120+2jj, 121+2jj]
//   jj <  60, ii == 0, k >= 1: batch k-1, row 179, cols [120+2jj, 121+2jj]
__global__ void finalize_kernel(float* __restrict__ out) {
    int v = blockIdx.x * blockDim.x + threadIdx.x;
    if (v >= NV) return;

    float* cont    = out;
    float* counter = out + NC;
    float* timer   = out + NC + NV;
    float* dxo     = out + NC + 2 * NV;
    float* dyo     = out + NC + 3 * NV;

    int k  = v / VPB;
    int rr = v - k * VPB;
    int ii = rr / WV;
    int jj = rr - ii * WV;

    const float2* Cb = g_ct + k * (HH * WW);
    int re = (2 * ii) * WW + 2 * jj;    // even row (2ii) base
    int ro = re + WW;                   // odd row (2ii+1) base
    float2 c00 = Cb[re], c01 = Cb[re + 1];
    float2 c10 = Cb[ro], c11 = Cb[ro + 1];

    // container output (full-res counts) — 2x2 block tiles the grid exactly
    int cb = k * (HH * WW);
    cont[cb + re]     = c00.x;
    cont[cb + re + 1] = c01.x;
    cont[cb + ro]     = c10.x;
    cont[cb + ro + 1] = c11.x;

    // strided diffs on the full-res histogram
    dxo[v] = (c10.x - c11.x) + (c00.x - c01.x);
    dyo[v] = (c00.x - c10.x) + (c01.x - c11.x);

    float Tk = __uint_as_float(g_small[2 + k]);
    if (Tk == 0.0f) Tk = 1.0f;

    float cnt = c00.x + c01.x;
    float ts  = c00.y + c01.y;
    float tn;

    if (jj >= WV / 2) {
        float2 o0 = Cb[ro - 120], o1 = Cb[ro - 119];
        cnt += o0.x + o1.x;  ts += o0.y + o1.y;
        tn = ts / Tk;
    } else if (ii >= 1) {
        float2 o0 = Cb[re - 120], o1 = Cb[re - 119];
        cnt += o0.x + o1.x;  ts += o0.y + o1.y;
        tn = ts / Tk;
    } else {
        tn = ts / Tk;
        if (k > 0) {
            const float2* Cp = g_ct + (k - 1) * (HH * WW) + (HH - 1) * WW;
            float2 s0 = Cp[120 + 2 * jj];
            float2 s1 = Cp[121 + 2 * jj];
            float Tp = __uint_as_float(g_small[2 + k - 1]);
            if (Tp == 0.0f) Tp = 1.0f;
            cnt += s0.x + s1.x;
            tn  += (s0.y + s1.y) / Tp;
        }
    }

    counter[v] = cnt;
    timer[v]   = tn / (cnt == 0.0f ? 1.0f : cnt);
}

// ---------------------------------------------------------------------------
extern "C" void kernel_launch(void* const* d_in, const int* in_sizes, int n_in,
                              void* d_out, int out_size)
{
    const float* ev = (const float*)d_in[0];
    int n = in_sizes[0] / 5;
    float* out = (float*)d_out;

    // only 128 B to reset per replay: barrier counter + tmax slots
    void* p_sm = nullptr;  cudaGetSymbolAddress(&p_sm, g_small);
    cudaMemsetAsync(p_sm, 0, sizeof(unsigned) * 32);

    int nTiles = (n + TILE_EV - 1) / TILE_EV;
    scatter_kernel<<<GRID_SC, 256>>>(ev, n, nTiles);
    finalize_kernel<<<(NV + 255) / 256, 256>>>(out);
}